// round 1
// baseline (speedup 1.0000x reference)
#include <cuda_runtime.h>
#include <math.h>

// Problem constants
#define B    8
#define C    128
#define Fk   8       // f dimension of c_feats (k=0 is c0, k=1..7 are c_rest)
#define K    7       // f-1
#define H64  64
#define HW   4096    // 64*64
#define HP   256     // high-res H=W
#define NHWC 16      // hw chunks per batch (256 px each)
#define NCC  8       // channel chunks (16 ch each)
#define CPB  16      // channels per block (pass kernels)
#define PXB  256     // pixels per block == blockDim.x

#define OUT1_ELEMS ((size_t)B * 257 * HW)   // (8,257,64,64)
#define OUT2_ELEMS ((size_t)B * HW)         // (8,1,64,64)

// -------- scratch (no allocations allowed) --------
__device__ float g_t[B * HW];                      // t mask (0/1)
__device__ float g_m[B * K * HW];                  // per-k mask (0/1)
__device__ float g_partG[B * K * NHWC * NCC];      // partial G sums
__device__ float g_partS[B * K * NHWC];            // partial S sums
__device__ float g_gs[B * K];                      // final gs

// ============================================================
// Kernel 1: resize masks 256->64 (linear, antialias=False) + threshold
//   out[i,j] = avg of in[{4i+1,4i+2} x {4j+1,4j+2}] > 0.5
// ============================================================
__global__ void k_masks(const float* __restrict__ vt, const float* __restrict__ va) {
    int idx = blockIdx.x * blockDim.x + threadIdx.x;   // 0 .. B*HW-1
    int b  = idx / HW;
    int hw = idx % HW;
    int i  = hw / H64;
    int j  = hw % H64;
    int r0 = 4 * i + 1;
    int q0 = 4 * j + 1;

    {
        const float* p = vt + (size_t)b * HP * HP;
        float a = p[r0 * HP + q0];
        float bb = p[r0 * HP + q0 + 1];
        float ccv = p[(r0 + 1) * HP + q0];
        float dd = p[(r0 + 1) * HP + q0 + 1];
        float y = 0.5f * (0.5f * a + 0.5f * bb) + 0.5f * (0.5f * ccv + 0.5f * dd);
        g_t[idx] = (y > 0.5f) ? 1.0f : 0.0f;
    }
    #pragma unroll
    for (int k = 0; k < K; k++) {
        const float* q = va + ((size_t)b * K + k) * HP * HP;
        float a = q[r0 * HP + q0];
        float bb = q[r0 * HP + q0 + 1];
        float ccv = q[(r0 + 1) * HP + q0];
        float dd = q[(r0 + 1) * HP + q0 + 1];
        float y = 0.5f * (0.5f * a + 0.5f * bb) + 0.5f * (0.5f * ccv + 0.5f * dd);
        g_m[((size_t)b * K + k) * HW + hw] = (y > 0.5f) ? 1.0f : 0.0f;
    }
}

// ============================================================
// Kernel 2: partial reductions for S[b,k] and G[b,k]
//   grid: b(8) x hwchunk(16) x cchunk(8)  = 1024 blocks, 256 threads
//   thread = one pixel; loop over 16 channels; D[k] = sum_c c0*c_rest[k];
//   then G contribution = vmap[k]*D[k]; S contribution = vmap[k].
// ============================================================
__global__ void k_pass1(const float* __restrict__ feats) {
    int bid = blockIdx.x;
    int cc  = bid % NCC;
    int hwc = (bid / NCC) % NHWC;
    int b   = bid / (NCC * NHWC);
    int hw  = hwc * PXB + threadIdx.x;

    float t = g_t[b * HW + hw];
    float vm[K];
    #pragma unroll
    for (int k = 0; k < K; k++)
        vm[k] = t * g_m[((size_t)b * K + k) * HW + hw];

    float D[K];
    #pragma unroll
    for (int k = 0; k < K; k++) D[k] = 0.0f;

    const float* base = feats + ((size_t)(b * C + cc * CPB)) * Fk * HW + hw;
    #pragma unroll 4
    for (int c = 0; c < CPB; c++) {
        const float* p = base + (size_t)c * Fk * HW;
        float c0v = p[0];
        #pragma unroll
        for (int k = 0; k < K; k++)
            D[k] = fmaf(c0v, p[(size_t)(k + 1) * HW], D[k]);
    }

    float vals[14];
    #pragma unroll
    for (int k = 0; k < K; k++) { vals[k] = vm[k] * D[k]; vals[K + k] = vm[k]; }

    // block reduction of 14 scalars
    __shared__ float red[8][14];
    int lane = threadIdx.x & 31;
    int wrp  = threadIdx.x >> 5;
    #pragma unroll
    for (int v = 0; v < 14; v++) {
        float x = vals[v];
        #pragma unroll
        for (int o = 16; o > 0; o >>= 1) x += __shfl_down_sync(0xFFFFFFFFu, x, o);
        if (lane == 0) red[wrp][v] = x;
    }
    __syncthreads();
    if (threadIdx.x < 14) {
        float x = 0.0f;
        #pragma unroll
        for (int w = 0; w < 8; w++) x += red[w][threadIdx.x];
        int v = threadIdx.x;
        if (v < K) {
            g_partG[((size_t)(b * K + v) * NHWC + hwc) * NCC + cc] = x;
        } else if (cc == 0) {
            g_partS[(size_t)(b * K + (v - K)) * NHWC + hwc] = x;
        }
    }
}

// ============================================================
// Kernel 3: final gs[b,k]  (fixed-order, deterministic)
// ============================================================
__global__ void k_gs() {
    int i = threadIdx.x;          // b*K index
    if (i >= B * K) return;
    float G = 0.0f;
    #pragma unroll 8
    for (int j = 0; j < NHWC * NCC; j++) G += g_partG[(size_t)i * NHWC * NCC + j];
    float S = 0.0f;
    #pragma unroll
    for (int j = 0; j < NHWC; j++) S += g_partS[(size_t)i * NHWC + j];
    float gs;
    if (S < 1e-4f) gs = 0.0f;                 // zeros branch
    else           gs = G / (S * (float)C);   // gs_norm = v_sum * c_c
    g_gs[i] = gs;
}

// ============================================================
// Kernel 4: per-pixel masked softmax + weighted sum over k.
//   Visits blocks in REVERSE of pass1's order to hit pass1's tail in L2.
// ============================================================
__global__ void k_pass2(const float* __restrict__ feats, float* __restrict__ out,
                        int write_second) {
    int bid = (gridDim.x - 1) - blockIdx.x;   // reversed traversal
    int cc  = bid % NCC;
    int hwc = (bid / NCC) % NHWC;
    int b   = bid / (NCC * NHWC);

    __shared__ float sgs[K];
    if (threadIdx.x < K) sgs[threadIdx.x] = g_gs[b * K + threadIdx.x];
    __syncthreads();

    int hw = hwc * PXB + threadIdx.x;

    float m[K], mv[K];
    #pragma unroll
    for (int k = 0; k < K; k++) {
        m[k]  = g_m[((size_t)b * K + k) * HW + hw];
        mv[k] = sgs[k] * m[k];
    }
    float mx = mv[0];
    #pragma unroll
    for (int k = 1; k < K; k++) mx = fmaxf(mx, mv[k]);

    float e[K], s = 0.0f;
    #pragma unroll
    for (int k = 0; k < K; k++) { e[k] = expf(mv[k] - mx) * m[k]; s += e[k]; }
    if (s < 1e-4f) s += 1.0f;
    float inv = 1.0f / s;

    float cm[K];
    float cmask = 0.0f;
    #pragma unroll
    for (int k = 0; k < K; k++) { cm[k] = e[k] * inv; cmask += cm[k] * m[k]; }
    cmask = 1.0f - cmask;

    const float* base = feats + ((size_t)(b * C + cc * CPB)) * Fk * HW + hw;
    float* ob = out + (size_t)b * 257 * HW + hw;

    #pragma unroll 4
    for (int c = 0; c < CPB; c++) {
        const float* p = base + (size_t)c * Fk * HW;
        float c0v = p[0];
        float acc = 0.0f;
        #pragma unroll
        for (int k = 0; k < K; k++)
            acc = fmaf(p[(size_t)(k + 1) * HW], cm[k], acc);
        int ch = cc * CPB + c;
        ob[(size_t)ch * HW]         = c0v;   // channels [0,128): c0 copy
        ob[(size_t)(128 + ch) * HW] = acc;   // channels [128,256): c_out
    }
    if (cc == 0) {
        ob[(size_t)256 * HW] = cmask;        // channel 256: c_mask
        if (write_second)
            out[OUT1_ELEMS + (size_t)b * HW + hw] = cmask;  // 2nd tuple output
    }
}

// ============================================================
extern "C" void kernel_launch(void* const* d_in, const int* in_sizes, int n_in,
                              void* d_out, int out_size) {
    const float* feats = (const float*)d_in[0];   // c_feats (8,128,8,64,64)
    const float* vt    = (const float*)d_in[1];   // v_t     (8,1,256,256)
    const float* va    = (const float*)d_in[2];   // v_aligned (8,1,7,256,256)
    float* out = (float*)d_out;

    int write_second = ((size_t)out_size >= OUT1_ELEMS + OUT2_ELEMS) ? 1 : 0;

    k_masks<<<(B * HW) / 256, 256>>>(vt, va);
    k_pass1<<<B * NHWC * NCC, 256>>>(feats);
    k_gs<<<1, 64>>>();
    k_pass2<<<B * NHWC * NCC, 256>>>(feats, out, write_second);
}